// round 14
// baseline (speedup 1.0000x reference)
#include <cuda_runtime.h>
#include <cuda_bf16.h>
#include <cuda_fp16.h>
#include <cstdint>

// Problem constants (fixed-shape problem)
#define NN   50000
#define EE   1600000
#define DIN  256
#define DH   128
#define DOUT 64

#define SCAN_CHUNK 1024
#define SCAN_NBLK  ((NN + SCAN_CHUNK - 1) / SCAN_CHUNK)   // 49

// ---------------- device scratch ----------------------------------------------
__device__ __half g_xw1h[NN * DH];     // x@W1  (fp16, gather + self)
__device__ __half g_xw2h[NN * DOUT];   // h1@W2 (fp16)
__device__ float g_deg [NN];
__device__ float g_dinv[NN];
__device__ int   g_cnt   [NN];
__device__ int   g_rowptr[NN + 1];
__device__ int   g_wptr  [NN];
__device__ int   g_blocksum[SCAN_NBLK];
__device__ int   g_blockoff[SCAN_NBLK];
__device__ int   g_src[EE];            // CSR-by-target: source node ids
__device__ float g_ewn[EE];            // dinv[src] * w  per edge (CSR order)
// split-bf16 activations (row-major [M][K])
__device__ __nv_bfloat16 g_xhi[NN * DIN];
__device__ __nv_bfloat16 g_xlo[NN * DIN];
__device__ __nv_bfloat16 g_h1hi[NN * DH];
__device__ __nv_bfloat16 g_h1lo[NN * DH];
// split-bf16 weights, transposed [N][K]
__device__ __nv_bfloat16 g_w1hi[DH  * DIN];
__device__ __nv_bfloat16 g_w1lo[DH  * DIN];
__device__ __nv_bfloat16 g_w2hi[DOUT * DH];
__device__ __nv_bfloat16 g_w2lo[DOUT * DH];

// ---------------- setup kernels ------------------------------------------------
__global__ void init_kernel() {
    int i = blockIdx.x * blockDim.x + threadIdx.x;
    if (i < NN) { g_cnt[i] = 0; g_deg[i] = 1.0f; /* self-loop weight */ }
}

__global__ void count_kernel(const int* __restrict__ col, const float* __restrict__ w) {
    int e = blockIdx.x * blockDim.x + threadIdx.x;
    if (e < EE) {
        int c = __ldg(&col[e]);
        atomicAdd(&g_cnt[c], 1);
        atomicAdd(&g_deg[c], __ldg(&w[e]));
    }
}

__global__ void dinv_kernel() {
    int i = blockIdx.x * blockDim.x + threadIdx.x;
    if (i < NN) g_dinv[i] = rsqrtf(g_deg[i]);
}

__global__ __launch_bounds__(SCAN_CHUNK) void scanA_kernel() {
    __shared__ int warpsum[32];
    __shared__ int warpoff[32];
    int tid = threadIdx.x, lane = tid & 31, wid = tid >> 5;
    int gid = blockIdx.x * SCAN_CHUNK + tid;
    int v = (gid < NN) ? g_cnt[gid] : 0;
    int incl = v;
    #pragma unroll
    for (int o = 1; o < 32; o <<= 1) {
        int t = __shfl_up_sync(0xffffffffu, incl, o);
        if (lane >= o) incl += t;
    }
    if (lane == 31) warpsum[wid] = incl;
    __syncthreads();
    if (wid == 0) {
        int s = warpsum[lane];
        int si = s;
        #pragma unroll
        for (int o = 1; o < 32; o <<= 1) {
            int t = __shfl_up_sync(0xffffffffu, si, o);
            if (lane >= o) si += t;
        }
        warpoff[lane] = si - s;
    }
    __syncthreads();
    int ex = warpoff[wid] + incl - v;
    if (gid < NN) g_rowptr[gid] = ex;
    if (tid == SCAN_CHUNK - 1) g_blocksum[blockIdx.x] = ex + v;
}

__global__ void scanB_kernel() {
    if (threadIdx.x == 0) {
        int run = 0;
        #pragma unroll
        for (int b = 0; b < SCAN_NBLK; b++) {
            g_blockoff[b] = run;
            run += g_blocksum[b];
        }
    }
}

__global__ void scanC_kernel() {
    int i = blockIdx.x * blockDim.x + threadIdx.x;
    if (i < NN) {
        int v = g_rowptr[i] + g_blockoff[i / SCAN_CHUNK];
        g_rowptr[i] = v;
        g_wptr[i]   = v;
    }
    if (i == 0) g_rowptr[NN] = EE;
}

__global__ void scatter_kernel(const int* __restrict__ row, const int* __restrict__ col,
                               const float* __restrict__ w) {
    int e = blockIdx.x * blockDim.x + threadIdx.x;
    if (e < EE) {
        int c = __ldg(&col[e]);
        int r = __ldg(&row[e]);
        int p = atomicAdd(&g_wptr[c], 1);
        g_src[p] = r;
        g_ewn[p] = __ldg(&w[e]) * g_dinv[r];
    }
}

// ---- weight split+transpose: W[K][N] fp32 -> hi/lo bf16 [N][K] ----------------
__global__ void convert_w_kernel(const float* __restrict__ W,
                                 __nv_bfloat16* __restrict__ hi,
                                 __nv_bfloat16* __restrict__ lo,
                                 int K, int N)
{
    int i = blockIdx.x * blockDim.x + threadIdx.x;
    if (i < K * N) {
        int k = i / N, n = i % N;
        float v = __ldg(&W[i]);
        __nv_bfloat16 h = __float2bfloat16_rn(v);
        hi[(size_t)n * K + k] = h;
        lo[(size_t)n * K + k] = __float2bfloat16_rn(v - __bfloat162float(h));
    }
}

// ---- activation split: A[M][K] fp32 -> hi/lo bf16 same layout -----------------
__global__ __launch_bounds__(256) void convert_x_kernel(
    const float* __restrict__ A,
    __nv_bfloat16* __restrict__ hi, __nv_bfloat16* __restrict__ lo, int total4)
{
    int i = blockIdx.x * blockDim.x + threadIdx.x;
    if (i < total4) {
        float4 v = __ldg(&((const float4*)A)[i]);
        __nv_bfloat16 hx = __float2bfloat16_rn(v.x);
        __nv_bfloat16 hy = __float2bfloat16_rn(v.y);
        __nv_bfloat16 hz = __float2bfloat16_rn(v.z);
        __nv_bfloat16 hw = __float2bfloat16_rn(v.w);
        uint32_t h01 = ((uint32_t)__bfloat16_as_ushort(hy) << 16) | __bfloat16_as_ushort(hx);
        uint32_t h23 = ((uint32_t)__bfloat16_as_ushort(hw) << 16) | __bfloat16_as_ushort(hz);
        ((uint2*)hi)[i] = make_uint2(h01, h23);
        __nv_bfloat16 lx = __float2bfloat16_rn(v.x - __bfloat162float(hx));
        __nv_bfloat16 ly = __float2bfloat16_rn(v.y - __bfloat162float(hy));
        __nv_bfloat16 lz = __float2bfloat16_rn(v.z - __bfloat162float(hz));
        __nv_bfloat16 lw = __float2bfloat16_rn(v.w - __bfloat162float(hw));
        uint32_t l01 = ((uint32_t)__bfloat16_as_ushort(ly) << 16) | __bfloat16_as_ushort(lx);
        uint32_t l23 = ((uint32_t)__bfloat16_as_ushort(lw) << 16) | __bfloat16_as_ushort(lz);
        ((uint2*)lo)[i] = make_uint2(l01, l23);
    }
}

// ---------------- mma.sync split-bf16 GEMM (A+B in SMEM, double-buffered) ------
__device__ __forceinline__ void mma_bf16(float* c, const uint32_t* a, const uint32_t* b) {
    asm volatile(
        "mma.sync.aligned.m16n8k16.row.col.f32.bf16.bf16.f32 "
        "{%0,%1,%2,%3}, {%4,%5,%6,%7}, {%8,%9}, {%0,%1,%2,%3};\n"
        : "+f"(c[0]), "+f"(c[1]), "+f"(c[2]), "+f"(c[3])
        : "r"(a[0]), "r"(a[1]), "r"(a[2]), "r"(a[3]), "r"(b[0]), "r"(b[1]));
}

__device__ __forceinline__ void ldmatrix_x4(uint32_t* r, uint32_t saddr) {
    asm volatile("ldmatrix.sync.aligned.m8n8.x4.shared.b16 {%0,%1,%2,%3}, [%4];"
                 : "=r"(r[0]), "=r"(r[1]), "=r"(r[2]), "=r"(r[3]) : "r"(saddr));
}

__device__ __forceinline__ void ldmatrix_x2(uint32_t* r, uint32_t saddr) {
    asm volatile("ldmatrix.sync.aligned.m8n8.x2.shared.b16 {%0,%1}, [%2];"
                 : "=r"(r[0]), "=r"(r[1]) : "r"(saddr));
}

__device__ __forceinline__ void cp_async16(uint32_t saddr, const void* gaddr) {
    asm volatile("cp.async.ca.shared.global [%0], [%1], 16;"
                 :: "r"(saddr), "l"(gaddr));
}
__device__ __forceinline__ void cp_commit() {
    asm volatile("cp.async.commit_group;");
}
template<int N>
__device__ __forceinline__ void cp_wait() {
    asm volatile("cp.async.wait_group %0;" :: "n"(N));
}

// SMEM rows: 32 bf16 data, stride 40 halfs (80B) -> conflict-free ldmatrix
#define TSTRIDE 40

// CTA tile 64 x NB. 8 warps = 2 rows x 4 cols; warp tile 32 x NB/4.
// Double-buffered; 2 CTAs/SM (validated best config, R11).
template<int KTOT, int NB>
__global__ __launch_bounds__(256, 2) void mma_gemm_smem_kernel(
    const __nv_bfloat16* __restrict__ Ahi,
    const __nv_bfloat16* __restrict__ Alo,
    const __nv_bfloat16* __restrict__ Bthi,
    const __nv_bfloat16* __restrict__ Btlo,
    __half* __restrict__ Ch, int M)
{
    constexpr int NK = KTOT / 32;
    constexpr int NTILES = (NB / 4) / 8;
    constexpr uint32_t SM_A_HI = 0;
    constexpr uint32_t SM_A_LO = 64 * TSTRIDE * 2;          // 5120
    constexpr uint32_t SM_B_HI = 2 * 64 * TSTRIDE * 2;      // 10240
    constexpr uint32_t SM_B_LO = SM_B_HI + NB * TSTRIDE * 2;
    constexpr uint32_t STAGE   = SM_B_LO + NB * TSTRIDE * 2;

    extern __shared__ __align__(16) char smem[];

    int tid  = threadIdx.x;
    int wid  = tid >> 5, lane = tid & 31;
    int g    = lane >> 2, tig = lane & 3;
    int wRow = wid & 1, wCol = wid >> 1;
    int rowBase = blockIdx.x * 64 + wRow * 32;
    int ctaRow  = blockIdx.x * 64;
    int colBase = wCol * (NB / 4);

    uint32_t sbase = 0;
    { uint32_t a; asm("{ .reg .u64 t; cvta.to.shared.u64 t, %1; cvt.u32.u64 %0, t; }"
                      : "=r"(a) : "l"((const void*)smem)); sbase = a; }

    auto load_tile = [&](int kt, int stage) {
        int kk = kt * 32;
        uint32_t sb = sbase + (uint32_t)stage * STAGE;
        // A: 64 rows x 4 chunks(16B) -> one per thread per array
        {
            int r = tid >> 2, c = tid & 3;
            int gr = min(ctaRow + r, M - 1);
            size_t goff = (size_t)gr * KTOT + kk + c * 8;
            uint32_t soff = (uint32_t)((r * TSTRIDE + c * 8) * 2);
            cp_async16(sb + SM_A_HI + soff, Ahi + goff);
            cp_async16(sb + SM_A_LO + soff, Alo + goff);
        }
        // B: NB rows x 4 chunks per array
        #pragma unroll
        for (int it = 0; it < (NB * 4) / 256; it++) {
            int chunk = it * 256 + tid;
            int n = chunk >> 2, c = chunk & 3;
            size_t goff = (size_t)n * KTOT + kk + c * 8;
            uint32_t soff = (uint32_t)((n * TSTRIDE + c * 8) * 2);
            cp_async16(sb + SM_B_HI + soff, Bthi + goff);
            cp_async16(sb + SM_B_LO + soff, Btlo + goff);
        }
        cp_commit();
    };

    float c[2][NTILES][4];
    #pragma unroll
    for (int mt = 0; mt < 2; mt++)
        #pragma unroll
        for (int nt = 0; nt < NTILES; nt++)
            #pragma unroll
            for (int i = 0; i < 4; i++) c[mt][nt][i] = 0.f;

    load_tile(0, 0);

    for (int kt = 0; kt < NK; kt++) {
        if (kt + 1 < NK) load_tile(kt + 1, (kt + 1) & 1);
        if (kt + 1 < NK) cp_wait<1>(); else cp_wait<0>();
        __syncthreads();

        uint32_t sb = sbase + (uint32_t)(kt & 1) * STAGE;

        #pragma unroll
        for (int ksub = 0; ksub < 2; ksub++) {
            // A fragments via ldmatrix.x4
            uint32_t ahi[2][4], alo[2][4];
            #pragma unroll
            for (int mt = 0; mt < 2; mt++) {
                int r = wRow * 32 + mt * 16 + (lane & 15);
                uint32_t off = (uint32_t)((r * TSTRIDE + ksub * 16 + ((lane >> 4) & 1) * 8) * 2);
                ldmatrix_x4(ahi[mt], sb + SM_A_HI + off);
                ldmatrix_x4(alo[mt], sb + SM_A_LO + off);
            }
            // B fragments via ldmatrix.x2 from SMEM
            uint32_t bhi[NTILES][2], blo[NTILES][2];
            int l = lane & 15;
            int brow = l & 7;           // n within 8-row tile
            int bmat = (l >> 3) & 1;    // 0: k 0-7, 1: k 8-15
            #pragma unroll
            for (int nt = 0; nt < NTILES; nt++) {
                uint32_t off = (uint32_t)(((colBase + nt * 8 + brow) * TSTRIDE
                                           + ksub * 16 + bmat * 8) * 2);
                ldmatrix_x2(bhi[nt], sb + SM_B_HI + off);
                ldmatrix_x2(blo[nt], sb + SM_B_LO + off);
            }
            #pragma unroll
            for (int mt = 0; mt < 2; mt++)
                #pragma unroll
                for (int nt = 0; nt < NTILES; nt++) {
                    mma_bf16(c[mt][nt], ahi[mt], bhi[nt]);
                    mma_bf16(c[mt][nt], ahi[mt], blo[nt]);
                    mma_bf16(c[mt][nt], alo[mt], bhi[nt]);
                }
        }
        __syncthreads();
    }

    // epilogue: fp16 only
    #pragma unroll
    for (int mt = 0; mt < 2; mt++) {
        int r0 = rowBase + mt * 16 + g;
        int r1 = r0 + 8;
        #pragma unroll
        for (int nt = 0; nt < NTILES; nt++) {
            int cc = colBase + nt * 8 + tig * 2;
            if (r0 < M)
                *(__half2*)&Ch[(size_t)r0 * NB + cc] =
                    __float22half2_rn(make_float2(c[mt][nt][0], c[mt][nt][1]));
            if (r1 < M)
                *(__half2*)&Ch[(size_t)r1 * NB + cc] =
                    __float22half2_rn(make_float2(c[mt][nt][2], c[mt][nt][3]));
        }
    }
}

// ---------------- warp-per-node aggregation, multi-edge vectorized -------------
// fp16 gathers: D=128 -> 2 edges per LDG.128 (16 lanes/row); D=64 -> 4 edges.
// fp32 accumulation; out[i,f] = di*sum + di^2*self + bias.
template<int D, bool RELU, bool SOFTMAX, bool SPLIT>
__global__ __launch_bounds__(256) void aggregate_warp_kernel(
    const __half* __restrict__ xwh, const float* __restrict__ bias,
    float* __restrict__ out,
    __nv_bfloat16* __restrict__ outhi, __nv_bfloat16* __restrict__ outlo)
{
    constexpr int WPB = 8;
    int wid  = threadIdx.x >> 5;
    int lane = threadIdx.x & 31;
    int node = blockIdx.x * WPB + wid;
    if (node >= NN) return;

    int p0 = g_rowptr[node], p1 = g_rowptr[node + 1];
    float di = g_dinv[node];
    const uint4* xh = (const uint4*)xwh;          // 8 halves per uint4

    if constexpr (D == 128) {
        int half = lane >> 4;        // 0/1: which edge of the pair
        int sub  = lane & 15;        // 16B chunk within the 256B row
        float acc[8];
        #pragma unroll
        for (int t = 0; t < 8; t++) acc[t] = 0.f;

        for (int base = p0; base < p1; base += 32) {
            int idx = base + lane;
            int s = 0; float wv = 0.f;
            if (idx < p1) { s = g_src[idx]; wv = g_ewn[idx]; }
            int c = min(32, p1 - base);
            #pragma unroll 4
            for (int j = 0; j < 16 && 2 * j < c; j++) {
                int e = 2 * j + half;
                int   sj = __shfl_sync(0xffffffffu, s,  e);
                float wj = __shfl_sync(0xffffffffu, wv, e);
                if (e < c) {
                    uint4 hv = __ldg(&xh[(size_t)sj * 16 + sub]);
                    float2 f;
                    f = __half22float2(*(__half2*)&hv.x); acc[0] += wj * f.x; acc[1] += wj * f.y;
                    f = __half22float2(*(__half2*)&hv.y); acc[2] += wj * f.x; acc[3] += wj * f.y;
                    f = __half22float2(*(__half2*)&hv.z); acc[4] += wj * f.x; acc[5] += wj * f.y;
                    f = __half22float2(*(__half2*)&hv.w); acc[6] += wj * f.x; acc[7] += wj * f.y;
                }
            }
        }
        // combine the two edge-halves (lanes L and L+16 hold partials for same feats)
        #pragma unroll
        for (int t = 0; t < 8; t++)
            acc[t] += __shfl_xor_sync(0xffffffffu, acc[t], 16);

        // this lane finalizes feats fb..fb+3
        int fb = sub * 8 + half * 4;
        float d2 = di * di;
        uint2 sv = __ldg((const uint2*)&xwh[(size_t)node * 128 + fb]);
        float2 s01 = __half22float2(*(__half2*)&sv.x);
        float2 s23 = __half22float2(*(__half2*)&sv.y);
        float4 bv  = __ldg((const float4*)&bias[fb]);
        float4 r;
        r.x = di * acc[half * 4 + 0] + d2 * s01.x + bv.x;
        r.y = di * acc[half * 4 + 1] + d2 * s01.y + bv.y;
        r.z = di * acc[half * 4 + 2] + d2 * s23.x + bv.z;
        r.w = di * acc[half * 4 + 3] + d2 * s23.y + bv.w;
        if (RELU) {
            r.x = fmaxf(r.x, 0.f); r.y = fmaxf(r.y, 0.f);
            r.z = fmaxf(r.z, 0.f); r.w = fmaxf(r.w, 0.f);
        }
        if constexpr (SPLIT) {
            __nv_bfloat16 hx = __float2bfloat16_rn(r.x);
            __nv_bfloat16 hy = __float2bfloat16_rn(r.y);
            __nv_bfloat16 hz = __float2bfloat16_rn(r.z);
            __nv_bfloat16 hw = __float2bfloat16_rn(r.w);
            uint32_t h01 = ((uint32_t)__bfloat16_as_ushort(hy) << 16) | __bfloat16_as_ushort(hx);
            uint32_t h23 = ((uint32_t)__bfloat16_as_ushort(hw) << 16) | __bfloat16_as_ushort(hz);
            ((uint2*)outhi)[(size_t)node * 32 + (fb >> 2)] = make_uint2(h01, h23);
            __nv_bfloat16 lx = __float2bfloat16_rn(r.x - __bfloat162float(hx));
            __nv_bfloat16 ly = __float2bfloat16_rn(r.y - __bfloat162float(hy));
            __nv_bfloat16 lz = __float2bfloat16_rn(r.z - __bfloat162float(hz));
            __nv_bfloat16 lw = __float2bfloat16_rn(r.w - __bfloat162float(hw));
            uint32_t l01 = ((uint32_t)__bfloat16_as_ushort(ly) << 16) | __bfloat16_as_ushort(lx);
            uint32_t l23 = ((uint32_t)__bfloat16_as_ushort(lw) << 16) | __bfloat16_as_ushort(lz);
            ((uint2*)outlo)[(size_t)node * 32 + (fb >> 2)] = make_uint2(l01, l23);
        } else {
            *(float4*)&out[(size_t)node * 128 + fb] = r;
        }
    } else {
        // D == 64: 128B rows, 8 lanes x 16B -> 4 edges per warp-LDG
        int q   = lane >> 3;         // 0..3: which edge of the quad
        int sub = lane & 7;          // 16B chunk within the 128B row
        float acc[8];
        #pragma unroll
        for (int t = 0; t < 8; t++) acc[t] = 0.f;

        for (int base = p0; base < p1; base += 32) {
            int idx = base + lane;
            int s = 0; float wv = 0.f;
            if (idx < p1) { s = g_src[idx]; wv = g_ewn[idx]; }
            int c = min(32, p1 - base);
            #pragma unroll 2
            for (int j = 0; j < 8 && 4 * j < c; j++) {
                int e = 4 * j + q;
                int   sj = __shfl_sync(0xffffffffu, s,  e);
                float wj = __shfl_sync(0xffffffffu, wv, e);
                if (e < c) {
                    uint4 hv = __ldg(&xh[(size_t)sj * 8 + sub]);
                    float2 f;
                    f = __half22float2(*(__half2*)&hv.x); acc[0] += wj * f.x; acc[1] += wj * f.y;
                    f = __half22float2(*(__half2*)&hv.y); acc[2] += wj * f.x; acc[3] += wj * f.y;
                    f = __half22float2(*(__half2*)&hv.z); acc[4] += wj * f.x; acc[5] += wj * f.y;
                    f = __half22float2(*(__half2*)&hv.w); acc[6] += wj * f.x; acc[7] += wj * f.y;
                }
            }
        }
        // combine the four edge-quarters
        #pragma unroll
        for (int t = 0; t < 8; t++) {
            acc[t] += __shfl_xor_sync(0xffffffffu, acc[t], 8);
            acc[t] += __shfl_xor_sync(0xffffffffu, acc[t], 16);
        }

        // this lane finalizes feats fb, fb+1
        int fb = sub * 8 + q * 2;
        float d2 = di * di;
        uint32_t sv = __ldg((const uint32_t*)&xwh[(size_t)node * 64 + fb]);
        float2 sf = __half22float2(*(__half2*)&sv);
        float2 bv = __ldg((const float2*)&bias[fb]);
        float rx = di * acc[q * 2 + 0] + d2 * sf.x + bv.x;
        float ry = di * acc[q * 2 + 1] + d2 * sf.y + bv.y;
        if (RELU) { rx = fmaxf(rx, 0.f); ry = fmaxf(ry, 0.f); }
        if (SOFTMAX) {
            float m = fmaxf(rx, ry);
            #pragma unroll
            for (int o = 16; o > 0; o >>= 1)
                m = fmaxf(m, __shfl_xor_sync(0xffffffffu, m, o));
            float sum = expf(rx - m) + expf(ry - m);
            #pragma unroll
            for (int o = 16; o > 0; o >>= 1)
                sum += __shfl_xor_sync(0xffffffffu, sum, o);
            float ls = m + logf(sum);
            rx -= ls; ry -= ls;
        }
        *(float2*)&out[(size_t)node * 64 + fb] = make_float2(rx, ry);
    }
}

// ---------------- launch -------------------------------------------------------
extern "C" void kernel_launch(void* const* d_in, const int* in_sizes, int n_in,
                              void* d_out, int out_size)
{
    const float* x  = (const float*)d_in[0];
    const int*   ei = (const int*)  d_in[1];
    const float* ew = (const float*)d_in[2];
    const float* W1 = (const float*)d_in[3];
    const float* b1 = (const float*)d_in[4];
    const float* W2 = (const float*)d_in[5];
    const float* b2 = (const float*)d_in[6];
    float* out = (float*)d_out;

    const int* row = ei;          // sources
    const int* col = ei + EE;     // targets

    void *p_xw1h, *p_xw2h, *p_xhi, *p_xlo, *p_h1hi, *p_h1lo;
    void *p_w1hi, *p_w1lo, *p_w2hi, *p_w2lo;
    cudaGetSymbolAddress(&p_xw1h, g_xw1h);
    cudaGetSymbolAddress(&p_xw2h, g_xw2h);
    cudaGetSymbolAddress(&p_xhi, g_xhi);
    cudaGetSymbolAddress(&p_xlo, g_xlo);
    cudaGetSymbolAddress(&p_h1hi, g_h1hi);
    cudaGetSymbolAddress(&p_h1lo, g_h1lo);
    cudaGetSymbolAddress(&p_w1hi, g_w1hi);
    cudaGetSymbolAddress(&p_w1lo, g_w1lo);
    cudaGetSymbolAddress(&p_w2hi, g_w2hi);
    cudaGetSymbolAddress(&p_w2lo, g_w2lo);
    __half* xw1h = (__half*)p_xw1h;
    __half* xw2h = (__half*)p_xw2h;
    __nv_bfloat16* xhi  = (__nv_bfloat16*)p_xhi;
    __nv_bfloat16* xlo  = (__nv_bfloat16*)p_xlo;
    __nv_bfloat16* h1hi = (__nv_bfloat16*)p_h1hi;
    __nv_bfloat16* h1lo = (__nv_bfloat16*)p_h1lo;
    __nv_bfloat16* w1hi = (__nv_bfloat16*)p_w1hi;
    __nv_bfloat16* w1lo = (__nv_bfloat16*)p_w1lo;
    __nv_bfloat16* w2hi = (__nv_bfloat16*)p_w2hi;
    __nv_bfloat16* w2lo = (__nv_bfloat16*)p_w2lo;

    const int TB = 256;
    const int GB = (NN + 63) / 64;   // 782

    // dynamic SMEM sizes: STAGE*2 (double buffer; 2 CTAs/SM)
    const int SMEM1 = 2 * (2 * 64 * TSTRIDE * 2 + 2 * DH   * TSTRIDE * 2);  // 61440
    const int SMEM2 = 2 * (2 * 64 * TSTRIDE * 2 + 2 * DOUT * TSTRIDE * 2);  // 40960
    cudaFuncSetAttribute(mma_gemm_smem_kernel<DIN, DH>,
                         cudaFuncAttributeMaxDynamicSharedMemorySize, SMEM1);
    cudaFuncSetAttribute(mma_gemm_smem_kernel<DH, DOUT>,
                         cudaFuncAttributeMaxDynamicSharedMemorySize, SMEM2);

    // fork: CSR branch on default stream, GEMM-prep branch on s2
    cudaStream_t s2;
    cudaStreamCreateWithFlags(&s2, cudaStreamNonBlocking);
    cudaEvent_t evFork, evJoin;
    cudaEventCreateWithFlags(&evFork, cudaEventDisableTiming);
    cudaEventCreateWithFlags(&evJoin, cudaEventDisableTiming);
    cudaEventRecord(evFork, 0);
    cudaStreamWaitEvent(s2, evFork, 0);

    // --- branch A (s2): conversions needed by GEMM1, then GEMM1 ---
    convert_w_kernel<<<(DIN * DH + TB - 1) / TB, TB, 0, s2>>>(W1, w1hi, w1lo, DIN, DH);
    convert_x_kernel<<<(NN * DIN / 4 + TB - 1) / TB, TB, 0, s2>>>(x, xhi, xlo, NN * DIN / 4);
    mma_gemm_smem_kernel<DIN, DH><<<GB, 256, SMEM1, s2>>>(xhi, xlo, w1hi, w1lo, xw1h, NN);
    cudaEventRecord(evJoin, s2);

    // --- branch B (default): CSR build + degree norm + W2 conversion ---
    convert_w_kernel<<<(DH * DOUT + TB - 1) / TB, TB>>>(W2, w2hi, w2lo, DH, DOUT);
    init_kernel   <<<(NN + TB - 1) / TB, TB>>>();
    count_kernel  <<<(EE + TB - 1) / TB, TB>>>(col, ew);
    dinv_kernel   <<<(NN + TB - 1) / TB, TB>>>();
    scanA_kernel  <<<SCAN_NBLK, SCAN_CHUNK>>>();
    scanB_kernel  <<<1, 32>>>();
    scanC_kernel  <<<(NN + TB - 1) / TB, TB>>>();
    scatter_kernel<<<(EE + TB - 1) / TB, TB>>>(row, col, ew);

    // join
    cudaStreamWaitEvent(0, evJoin, 0);

    // layer 1 aggregate (+relu, emit split bf16)
    aggregate_warp_kernel<DH, true, false, true><<<(NN + 7) / 8, 256>>>(
        xw1h, b1, nullptr, h1hi, h1lo);

    // layer 2: GEMM -> aggregate + log_softmax
    mma_gemm_smem_kernel<DH, DOUT><<<GB, 256, SMEM2>>>(h1hi, h1lo, w2hi, w2lo, xw2h, NN);
    aggregate_warp_kernel<DOUT, false, true, false><<<(NN + 7) / 8, 256>>>(
        xw2h, b2, out, nullptr, nullptr);
}

// round 16
// speedup vs baseline: 1.0033x; 1.0033x over previous
#include <cuda_runtime.h>
#include <cuda_bf16.h>
#include <cuda_fp16.h>
#include <cstdint>

// Problem constants (fixed-shape problem)
#define NN   50000
#define EE   1600000
#define DIN  256
#define DH   128
#define DOUT 64

#define SCAN_CHUNK 1024
#define SCAN_NBLK  ((NN + SCAN_CHUNK - 1) / SCAN_CHUNK)   // 49

// ---------------- device scratch ----------------------------------------------
__device__ __half g_xw1h[NN * DH];     // x@W1  (fp16, gather + self)
__device__ __half g_xw2h[NN * DOUT];   // h1@W2 (fp16)
__device__ float g_deg [NN];
__device__ float g_dinv[NN];
__device__ int   g_cnt   [NN];
__device__ int   g_rowptr[NN + 1];
__device__ int   g_wptr  [NN];
__device__ int   g_blocksum[SCAN_NBLK];
__device__ int   g_blockoff[SCAN_NBLK];
__device__ int   g_src[EE];            // CSR-by-target: source node ids
__device__ float g_ewn[EE];            // dinv[src] * w  per edge (CSR order)
// split-bf16 activations (row-major [M][K])
__device__ __nv_bfloat16 g_xhi[NN * DIN];
__device__ __nv_bfloat16 g_xlo[NN * DIN];
__device__ __nv_bfloat16 g_h1hi[NN * DH];
__device__ __nv_bfloat16 g_h1lo[NN * DH];
// split-bf16 weights, transposed [N][K]
__device__ __nv_bfloat16 g_w1hi[DH  * DIN];
__device__ __nv_bfloat16 g_w1lo[DH  * DIN];
__device__ __nv_bfloat16 g_w2hi[DOUT * DH];
__device__ __nv_bfloat16 g_w2lo[DOUT * DH];

// ---------------- setup kernels ------------------------------------------------
__global__ void init_kernel() {
    int i = blockIdx.x * blockDim.x + threadIdx.x;
    if (i < NN) { g_cnt[i] = 0; g_deg[i] = 1.0f; /* self-loop weight */ }
}

__global__ void count_kernel(const int* __restrict__ col, const float* __restrict__ w) {
    int e = blockIdx.x * blockDim.x + threadIdx.x;
    if (e < EE) {
        int c = __ldg(&col[e]);
        atomicAdd(&g_cnt[c], 1);
        atomicAdd(&g_deg[c], __ldg(&w[e]));
    }
}

__global__ void dinv_kernel() {
    int i = blockIdx.x * blockDim.x + threadIdx.x;
    if (i < NN) g_dinv[i] = rsqrtf(g_deg[i]);
}

__global__ __launch_bounds__(SCAN_CHUNK) void scanA_kernel() {
    __shared__ int warpsum[32];
    __shared__ int warpoff[32];
    int tid = threadIdx.x, lane = tid & 31, wid = tid >> 5;
    int gid = blockIdx.x * SCAN_CHUNK + tid;
    int v = (gid < NN) ? g_cnt[gid] : 0;
    int incl = v;
    #pragma unroll
    for (int o = 1; o < 32; o <<= 1) {
        int t = __shfl_up_sync(0xffffffffu, incl, o);
        if (lane >= o) incl += t;
    }
    if (lane == 31) warpsum[wid] = incl;
    __syncthreads();
    if (wid == 0) {
        int s = warpsum[lane];
        int si = s;
        #pragma unroll
        for (int o = 1; o < 32; o <<= 1) {
            int t = __shfl_up_sync(0xffffffffu, si, o);
            if (lane >= o) si += t;
        }
        warpoff[lane] = si - s;
    }
    __syncthreads();
    int ex = warpoff[wid] + incl - v;
    if (gid < NN) g_rowptr[gid] = ex;
    if (tid == SCAN_CHUNK - 1) g_blocksum[blockIdx.x] = ex + v;
}

__global__ void scanB_kernel() {
    if (threadIdx.x == 0) {
        int run = 0;
        #pragma unroll
        for (int b = 0; b < SCAN_NBLK; b++) {
            g_blockoff[b] = run;
            run += g_blocksum[b];
        }
    }
}

__global__ void scanC_kernel() {
    int i = blockIdx.x * blockDim.x + threadIdx.x;
    if (i < NN) {
        int v = g_rowptr[i] + g_blockoff[i / SCAN_CHUNK];
        g_rowptr[i] = v;
        g_wptr[i]   = v;
    }
    if (i == 0) g_rowptr[NN] = EE;
}

__global__ void scatter_kernel(const int* __restrict__ row, const int* __restrict__ col,
                               const float* __restrict__ w) {
    int e = blockIdx.x * blockDim.x + threadIdx.x;
    if (e < EE) {
        int c = __ldg(&col[e]);
        int r = __ldg(&row[e]);
        int p = atomicAdd(&g_wptr[c], 1);
        g_src[p] = r;
        g_ewn[p] = __ldg(&w[e]) * g_dinv[r];
    }
}

// ---- weight split+transpose: W[K][N] fp32 -> hi/lo bf16 [N][K] ----------------
__global__ void convert_w_kernel(const float* __restrict__ W,
                                 __nv_bfloat16* __restrict__ hi,
                                 __nv_bfloat16* __restrict__ lo,
                                 int K, int N)
{
    int i = blockIdx.x * blockDim.x + threadIdx.x;
    if (i < K * N) {
        int k = i / N, n = i % N;
        float v = __ldg(&W[i]);
        __nv_bfloat16 h = __float2bfloat16_rn(v);
        hi[(size_t)n * K + k] = h;
        lo[(size_t)n * K + k] = __float2bfloat16_rn(v - __bfloat162float(h));
    }
}

// ---- activation split: A[M][K] fp32 -> hi/lo bf16 same layout -----------------
__global__ __launch_bounds__(256) void convert_x_kernel(
    const float* __restrict__ A,
    __nv_bfloat16* __restrict__ hi, __nv_bfloat16* __restrict__ lo, int total4)
{
    int i = blockIdx.x * blockDim.x + threadIdx.x;
    if (i < total4) {
        float4 v = __ldg(&((const float4*)A)[i]);
        __nv_bfloat16 hx = __float2bfloat16_rn(v.x);
        __nv_bfloat16 hy = __float2bfloat16_rn(v.y);
        __nv_bfloat16 hz = __float2bfloat16_rn(v.z);
        __nv_bfloat16 hw = __float2bfloat16_rn(v.w);
        uint32_t h01 = ((uint32_t)__bfloat16_as_ushort(hy) << 16) | __bfloat16_as_ushort(hx);
        uint32_t h23 = ((uint32_t)__bfloat16_as_ushort(hw) << 16) | __bfloat16_as_ushort(hz);
        ((uint2*)hi)[i] = make_uint2(h01, h23);
        __nv_bfloat16 lx = __float2bfloat16_rn(v.x - __bfloat162float(hx));
        __nv_bfloat16 ly = __float2bfloat16_rn(v.y - __bfloat162float(hy));
        __nv_bfloat16 lz = __float2bfloat16_rn(v.z - __bfloat162float(hz));
        __nv_bfloat16 lw = __float2bfloat16_rn(v.w - __bfloat162float(hw));
        uint32_t l01 = ((uint32_t)__bfloat16_as_ushort(ly) << 16) | __bfloat16_as_ushort(lx);
        uint32_t l23 = ((uint32_t)__bfloat16_as_ushort(lw) << 16) | __bfloat16_as_ushort(lz);
        ((uint2*)lo)[i] = make_uint2(l01, l23);
    }
}

// ---------------- mma.sync split-bf16 GEMM (A+B in SMEM, double-buffered) ------
__device__ __forceinline__ void mma_bf16(float* c, const uint32_t* a, const uint32_t* b) {
    asm volatile(
        "mma.sync.aligned.m16n8k16.row.col.f32.bf16.bf16.f32 "
        "{%0,%1,%2,%3}, {%4,%5,%6,%7}, {%8,%9}, {%0,%1,%2,%3};\n"
        : "+f"(c[0]), "+f"(c[1]), "+f"(c[2]), "+f"(c[3])
        : "r"(a[0]), "r"(a[1]), "r"(a[2]), "r"(a[3]), "r"(b[0]), "r"(b[1]));
}

__device__ __forceinline__ void ldmatrix_x4(uint32_t* r, uint32_t saddr) {
    asm volatile("ldmatrix.sync.aligned.m8n8.x4.shared.b16 {%0,%1,%2,%3}, [%4];"
                 : "=r"(r[0]), "=r"(r[1]), "=r"(r[2]), "=r"(r[3]) : "r"(saddr));
}

__device__ __forceinline__ void ldmatrix_x2(uint32_t* r, uint32_t saddr) {
    asm volatile("ldmatrix.sync.aligned.m8n8.x2.shared.b16 {%0,%1}, [%2];"
                 : "=r"(r[0]), "=r"(r[1]) : "r"(saddr));
}

__device__ __forceinline__ void cp_async16(uint32_t saddr, const void* gaddr) {
    asm volatile("cp.async.ca.shared.global [%0], [%1], 16;"
                 :: "r"(saddr), "l"(gaddr));
}
__device__ __forceinline__ void cp_commit() {
    asm volatile("cp.async.commit_group;");
}
template<int N>
__device__ __forceinline__ void cp_wait() {
    asm volatile("cp.async.wait_group %0;" :: "n"(N));
}

// SMEM rows: 32 bf16 data, stride 40 halfs (80B) -> conflict-free ldmatrix
#define TSTRIDE 40

// CTA tile 64 x NB. 8 warps = 2 rows x 4 cols; warp tile 32 x NB/4.
// Double-buffered; 2 CTAs/SM (validated best config, R11).
template<int KTOT, int NB>
__global__ __launch_bounds__(256, 2) void mma_gemm_smem_kernel(
    const __nv_bfloat16* __restrict__ Ahi,
    const __nv_bfloat16* __restrict__ Alo,
    const __nv_bfloat16* __restrict__ Bthi,
    const __nv_bfloat16* __restrict__ Btlo,
    __half* __restrict__ Ch, int M)
{
    constexpr int NK = KTOT / 32;
    constexpr int NTILES = (NB / 4) / 8;
    constexpr uint32_t SM_A_HI = 0;
    constexpr uint32_t SM_A_LO = 64 * TSTRIDE * 2;          // 5120
    constexpr uint32_t SM_B_HI = 2 * 64 * TSTRIDE * 2;      // 10240
    constexpr uint32_t SM_B_LO = SM_B_HI + NB * TSTRIDE * 2;
    constexpr uint32_t STAGE   = SM_B_LO + NB * TSTRIDE * 2;

    extern __shared__ __align__(16) char smem[];

    int tid  = threadIdx.x;
    int wid  = tid >> 5, lane = tid & 31;
    int g    = lane >> 2, tig = lane & 3;
    int wRow = wid & 1, wCol = wid >> 1;
    int rowBase = blockIdx.x * 64 + wRow * 32;
    int ctaRow  = blockIdx.x * 64;
    int colBase = wCol * (NB / 4);

    uint32_t sbase = 0;
    { uint32_t a; asm("{ .reg .u64 t; cvta.to.shared.u64 t, %1; cvt.u32.u64 %0, t; }"
                      : "=r"(a) : "l"((const void*)smem)); sbase = a; }

    auto load_tile = [&](int kt, int stage) {
        int kk = kt * 32;
        uint32_t sb = sbase + (uint32_t)stage * STAGE;
        // A: 64 rows x 4 chunks(16B) -> one per thread per array
        {
            int r = tid >> 2, c = tid & 3;
            int gr = min(ctaRow + r, M - 1);
            size_t goff = (size_t)gr * KTOT + kk + c * 8;
            uint32_t soff = (uint32_t)((r * TSTRIDE + c * 8) * 2);
            cp_async16(sb + SM_A_HI + soff, Ahi + goff);
            cp_async16(sb + SM_A_LO + soff, Alo + goff);
        }
        // B: NB rows x 4 chunks per array
        #pragma unroll
        for (int it = 0; it < (NB * 4) / 256; it++) {
            int chunk = it * 256 + tid;
            int n = chunk >> 2, c = chunk & 3;
            size_t goff = (size_t)n * KTOT + kk + c * 8;
            uint32_t soff = (uint32_t)((n * TSTRIDE + c * 8) * 2);
            cp_async16(sb + SM_B_HI + soff, Bthi + goff);
            cp_async16(sb + SM_B_LO + soff, Btlo + goff);
        }
        cp_commit();
    };

    float c[2][NTILES][4];
    #pragma unroll
    for (int mt = 0; mt < 2; mt++)
        #pragma unroll
        for (int nt = 0; nt < NTILES; nt++)
            #pragma unroll
            for (int i = 0; i < 4; i++) c[mt][nt][i] = 0.f;

    load_tile(0, 0);

    for (int kt = 0; kt < NK; kt++) {
        if (kt + 1 < NK) load_tile(kt + 1, (kt + 1) & 1);
        if (kt + 1 < NK) cp_wait<1>(); else cp_wait<0>();
        __syncthreads();

        uint32_t sb = sbase + (uint32_t)(kt & 1) * STAGE;

        #pragma unroll
        for (int ksub = 0; ksub < 2; ksub++) {
            // A fragments via ldmatrix.x4
            uint32_t ahi[2][4], alo[2][4];
            #pragma unroll
            for (int mt = 0; mt < 2; mt++) {
                int r = wRow * 32 + mt * 16 + (lane & 15);
                uint32_t off = (uint32_t)((r * TSTRIDE + ksub * 16 + ((lane >> 4) & 1) * 8) * 2);
                ldmatrix_x4(ahi[mt], sb + SM_A_HI + off);
                ldmatrix_x4(alo[mt], sb + SM_A_LO + off);
            }
            // B fragments via ldmatrix.x2 from SMEM
            uint32_t bhi[NTILES][2], blo[NTILES][2];
            int l = lane & 15;
            int brow = l & 7;           // n within 8-row tile
            int bmat = (l >> 3) & 1;    // 0: k 0-7, 1: k 8-15
            #pragma unroll
            for (int nt = 0; nt < NTILES; nt++) {
                uint32_t off = (uint32_t)(((colBase + nt * 8 + brow) * TSTRIDE
                                           + ksub * 16 + bmat * 8) * 2);
                ldmatrix_x2(bhi[nt], sb + SM_B_HI + off);
                ldmatrix_x2(blo[nt], sb + SM_B_LO + off);
            }
            #pragma unroll
            for (int mt = 0; mt < 2; mt++)
                #pragma unroll
                for (int nt = 0; nt < NTILES; nt++) {
                    mma_bf16(c[mt][nt], ahi[mt], bhi[nt]);
                    mma_bf16(c[mt][nt], ahi[mt], blo[nt]);
                    mma_bf16(c[mt][nt], alo[mt], bhi[nt]);
                }
        }
        __syncthreads();
    }

    // epilogue: fp16 only
    #pragma unroll
    for (int mt = 0; mt < 2; mt++) {
        int r0 = rowBase + mt * 16 + g;
        int r1 = r0 + 8;
        #pragma unroll
        for (int nt = 0; nt < NTILES; nt++) {
            int cc = colBase + nt * 8 + tig * 2;
            if (r0 < M)
                *(__half2*)&Ch[(size_t)r0 * NB + cc] =
                    __float22half2_rn(make_float2(c[mt][nt][0], c[mt][nt][1]));
            if (r1 < M)
                *(__half2*)&Ch[(size_t)r1 * NB + cc] =
                    __float22half2_rn(make_float2(c[mt][nt][2], c[mt][nt][3]));
        }
    }
}

// ---------------- warp-per-node aggregation, multi-edge vectorized -------------
// fp16 gathers: D=128 -> 2 edges per LDG.128 (16 lanes/row); D=64 -> 4 edges.
// fp32 accumulation; out[i,f] = di*sum + di^2*self + bias.
template<int D, bool RELU, bool SOFTMAX, bool SPLIT>
__global__ __launch_bounds__(256) void aggregate_warp_kernel(
    const __half* __restrict__ xwh, const float* __restrict__ bias,
    float* __restrict__ out,
    __nv_bfloat16* __restrict__ outhi, __nv_bfloat16* __restrict__ outlo)
{
    constexpr int WPB = 8;
    int wid  = threadIdx.x >> 5;
    int lane = threadIdx.x & 31;
    int node = blockIdx.x * WPB + wid;
    if (node >= NN) return;

    int p0 = g_rowptr[node], p1 = g_rowptr[node + 1];
    float di = g_dinv[node];
    const uint4* xh = (const uint4*)xwh;          // 8 halves per uint4

    if constexpr (D == 128) {
        int half = lane >> 4;        // 0/1: which edge of the pair
        int sub  = lane & 15;        // 16B chunk within the 256B row
        float acc[8];
        #pragma unroll
        for (int t = 0; t < 8; t++) acc[t] = 0.f;

        for (int base = p0; base < p1; base += 32) {
            int idx = base + lane;
            int s = 0; float wv = 0.f;
            if (idx < p1) { s = g_src[idx]; wv = g_ewn[idx]; }
            int c = min(32, p1 - base);
            #pragma unroll 4
            for (int j = 0; j < 16 && 2 * j < c; j++) {
                int e = 2 * j + half;
                int   sj = __shfl_sync(0xffffffffu, s,  e);
                float wj = __shfl_sync(0xffffffffu, wv, e);
                if (e < c) {
                    uint4 hv = __ldg(&xh[(size_t)sj * 16 + sub]);
                    float2 f;
                    f = __half22float2(*(__half2*)&hv.x); acc[0] += wj * f.x; acc[1] += wj * f.y;
                    f = __half22float2(*(__half2*)&hv.y); acc[2] += wj * f.x; acc[3] += wj * f.y;
                    f = __half22float2(*(__half2*)&hv.z); acc[4] += wj * f.x; acc[5] += wj * f.y;
                    f = __half22float2(*(__half2*)&hv.w); acc[6] += wj * f.x; acc[7] += wj * f.y;
                }
            }
        }
        // combine the two edge-halves (lanes L and L+16 hold partials for same feats)
        #pragma unroll
        for (int t = 0; t < 8; t++)
            acc[t] += __shfl_xor_sync(0xffffffffu, acc[t], 16);

        // this lane finalizes feats fb..fb+3
        int fb = sub * 8 + half * 4;
        float d2 = di * di;
        uint2 sv = __ldg((const uint2*)&xwh[(size_t)node * 128 + fb]);
        float2 s01 = __half22float2(*(__half2*)&sv.x);
        float2 s23 = __half22float2(*(__half2*)&sv.y);
        float4 bv  = __ldg((const float4*)&bias[fb]);
        float4 r;
        r.x = di * acc[half * 4 + 0] + d2 * s01.x + bv.x;
        r.y = di * acc[half * 4 + 1] + d2 * s01.y + bv.y;
        r.z = di * acc[half * 4 + 2] + d2 * s23.x + bv.z;
        r.w = di * acc[half * 4 + 3] + d2 * s23.y + bv.w;
        if (RELU) {
            r.x = fmaxf(r.x, 0.f); r.y = fmaxf(r.y, 0.f);
            r.z = fmaxf(r.z, 0.f); r.w = fmaxf(r.w, 0.f);
        }
        if constexpr (SPLIT) {
            __nv_bfloat16 hx = __float2bfloat16_rn(r.x);
            __nv_bfloat16 hy = __float2bfloat16_rn(r.y);
            __nv_bfloat16 hz = __float2bfloat16_rn(r.z);
            __nv_bfloat16 hw = __float2bfloat16_rn(r.w);
            uint32_t h01 = ((uint32_t)__bfloat16_as_ushort(hy) << 16) | __bfloat16_as_ushort(hx);
            uint32_t h23 = ((uint32_t)__bfloat16_as_ushort(hw) << 16) | __bfloat16_as_ushort(hz);
            ((uint2*)outhi)[(size_t)node * 32 + (fb >> 2)] = make_uint2(h01, h23);
            __nv_bfloat16 lx = __float2bfloat16_rn(r.x - __bfloat162float(hx));
            __nv_bfloat16 ly = __float2bfloat16_rn(r.y - __bfloat162float(hy));
            __nv_bfloat16 lz = __float2bfloat16_rn(r.z - __bfloat162float(hz));
            __nv_bfloat16 lw = __float2bfloat16_rn(r.w - __bfloat162float(hw));
            uint32_t l01 = ((uint32_t)__bfloat16_as_ushort(ly) << 16) | __bfloat16_as_ushort(lx);
            uint32_t l23 = ((uint32_t)__bfloat16_as_ushort(lw) << 16) | __bfloat16_as_ushort(lz);
            ((uint2*)outlo)[(size_t)node * 32 + (fb >> 2)] = make_uint2(l01, l23);
        } else {
            *(float4*)&out[(size_t)node * 128 + fb] = r;
        }
    } else {
        // D == 64: 128B rows, 8 lanes x 16B -> 4 edges per warp-LDG
        int q   = lane >> 3;         // 0..3: which edge of the quad
        int sub = lane & 7;          // 16B chunk within the 128B row
        float acc[8];
        #pragma unroll
        for (int t = 0; t < 8; t++) acc[t] = 0.f;

        for (int base = p0; base < p1; base += 32) {
            int idx = base + lane;
            int s = 0; float wv = 0.f;
            if (idx < p1) { s = g_src[idx]; wv = g_ewn[idx]; }
            int c = min(32, p1 - base);
            #pragma unroll 2
            for (int j = 0; j < 8 && 4 * j < c; j++) {
                int e = 4 * j + q;
                int   sj = __shfl_sync(0xffffffffu, s,  e);
                float wj = __shfl_sync(0xffffffffu, wv, e);
                if (e < c) {
                    uint4 hv = __ldg(&xh[(size_t)sj * 8 + sub]);
                    float2 f;
                    f = __half22float2(*(__half2*)&hv.x); acc[0] += wj * f.x; acc[1] += wj * f.y;
                    f = __half22float2(*(__half2*)&hv.y); acc[2] += wj * f.x; acc[3] += wj * f.y;
                    f = __half22float2(*(__half2*)&hv.z); acc[4] += wj * f.x; acc[5] += wj * f.y;
                    f = __half22float2(*(__half2*)&hv.w); acc[6] += wj * f.x; acc[7] += wj * f.y;
                }
            }
        }
        // combine the four edge-quarters
        #pragma unroll
        for (int t = 0; t < 8; t++) {
            acc[t] += __shfl_xor_sync(0xffffffffu, acc[t], 8);
            acc[t] += __shfl_xor_sync(0xffffffffu, acc[t], 16);
        }

        // this lane finalizes feats fb, fb+1
        int fb = sub * 8 + q * 2;
        float d2 = di * di;
        uint32_t sv = __ldg((const uint32_t*)&xwh[(size_t)node * 64 + fb]);
        float2 sf = __half22float2(*(__half2*)&sv);
        float2 bv = __ldg((const float2*)&bias[fb]);
        float rx = di * acc[q * 2 + 0] + d2 * sf.x + bv.x;
        float ry = di * acc[q * 2 + 1] + d2 * sf.y + bv.y;
        if (RELU) { rx = fmaxf(rx, 0.f); ry = fmaxf(ry, 0.f); }
        if (SOFTMAX) {
            float m = fmaxf(rx, ry);
            #pragma unroll
            for (int o = 16; o > 0; o >>= 1)
                m = fmaxf(m, __shfl_xor_sync(0xffffffffu, m, o));
            float sum = expf(rx - m) + expf(ry - m);
            #pragma unroll
            for (int o = 16; o > 0; o >>= 1)
                sum += __shfl_xor_sync(0xffffffffu, sum, o);
            float ls = m + logf(sum);
            rx -= ls; ry -= ls;
        }
        *(float2*)&out[(size_t)node * 64 + fb] = make_float2(rx, ry);
    }
}

// ---------------- launch -------------------------------------------------------
extern "C" void kernel_launch(void* const* d_in, const int* in_sizes, int n_in,
                              void* d_out, int out_size)
{
    const float* x  = (const float*)d_in[0];
    const int*   ei = (const int*)  d_in[1];
    const float* ew = (const float*)d_in[2];
    const float* W1 = (const float*)d_in[3];
    const float* b1 = (const float*)d_in[4];
    const float* W2 = (const float*)d_in[5];
    const float* b2 = (const float*)d_in[6];
    float* out = (float*)d_out;

    const int* row = ei;          // sources
    const int* col = ei + EE;     // targets

    void *p_xw1h, *p_xw2h, *p_xhi, *p_xlo, *p_h1hi, *p_h1lo;
    void *p_w1hi, *p_w1lo, *p_w2hi, *p_w2lo;
    cudaGetSymbolAddress(&p_xw1h, g_xw1h);
    cudaGetSymbolAddress(&p_xw2h, g_xw2h);
    cudaGetSymbolAddress(&p_xhi, g_xhi);
    cudaGetSymbolAddress(&p_xlo, g_xlo);
    cudaGetSymbolAddress(&p_h1hi, g_h1hi);
    cudaGetSymbolAddress(&p_h1lo, g_h1lo);
    cudaGetSymbolAddress(&p_w1hi, g_w1hi);
    cudaGetSymbolAddress(&p_w1lo, g_w1lo);
    cudaGetSymbolAddress(&p_w2hi, g_w2hi);
    cudaGetSymbolAddress(&p_w2lo, g_w2lo);
    __half* xw1h = (__half*)p_xw1h;
    __half* xw2h = (__half*)p_xw2h;
    __nv_bfloat16* xhi  = (__nv_bfloat16*)p_xhi;
    __nv_bfloat16* xlo  = (__nv_bfloat16*)p_xlo;
    __nv_bfloat16* h1hi = (__nv_bfloat16*)p_h1hi;
    __nv_bfloat16* h1lo = (__nv_bfloat16*)p_h1lo;
    __nv_bfloat16* w1hi = (__nv_bfloat16*)p_w1hi;
    __nv_bfloat16* w1lo = (__nv_bfloat16*)p_w1lo;
    __nv_bfloat16* w2hi = (__nv_bfloat16*)p_w2hi;
    __nv_bfloat16* w2lo = (__nv_bfloat16*)p_w2lo;

    const int TB = 256;
    const int GB = (NN + 63) / 64;   // 782

    // dynamic SMEM sizes: STAGE*2 (double buffer; 2 CTAs/SM)
    const int SMEM1 = 2 * (2 * 64 * TSTRIDE * 2 + 2 * DH   * TSTRIDE * 2);  // 61440
    const int SMEM2 = 2 * (2 * 64 * TSTRIDE * 2 + 2 * DOUT * TSTRIDE * 2);  // 40960
    cudaFuncSetAttribute(mma_gemm_smem_kernel<DIN, DH>,
                         cudaFuncAttributeMaxDynamicSharedMemorySize, SMEM1);
    cudaFuncSetAttribute(mma_gemm_smem_kernel<DH, DOUT>,
                         cudaFuncAttributeMaxDynamicSharedMemorySize, SMEM2);

    // fork: CSR branch on default stream, GEMM-prep branch on s2
    cudaStream_t s2;
    cudaStreamCreateWithFlags(&s2, cudaStreamNonBlocking);
    cudaEvent_t evFork, evJoin;
    cudaEventCreateWithFlags(&evFork, cudaEventDisableTiming);
    cudaEventCreateWithFlags(&evJoin, cudaEventDisableTiming);
    cudaEventRecord(evFork, 0);
    cudaStreamWaitEvent(s2, evFork, 0);

    // --- branch A (s2): conversions + GEMM1 ---
    convert_w_kernel<<<(DIN * DH   + TB - 1) / TB, TB, 0, s2>>>(W1, w1hi, w1lo, DIN, DH);
    convert_w_kernel<<<(DH  * DOUT + TB - 1) / TB, TB, 0, s2>>>(W2, w2hi, w2lo, DH, DOUT);
    convert_x_kernel<<<(NN * DIN / 4 + TB - 1) / TB, TB, 0, s2>>>(x, xhi, xlo, NN * DIN / 4);
    mma_gemm_smem_kernel<DIN, DH><<<GB, 256, SMEM1, s2>>>(xhi, xlo, w1hi, w1lo, xw1h, NN);
    cudaEventRecord(evJoin, s2);

    // --- branch B (default): CSR build + degree norm ---
    init_kernel   <<<(NN + TB - 1) / TB, TB>>>();
    count_kernel  <<<(EE + TB - 1) / TB, TB>>>(col, ew);
    dinv_kernel   <<<(NN + TB - 1) / TB, TB>>>();
    scanA_kernel  <<<SCAN_NBLK, SCAN_CHUNK>>>();
    scanB_kernel  <<<1, 32>>>();
    scanC_kernel  <<<(NN + TB - 1) / TB, TB>>>();
    scatter_kernel<<<(EE + TB - 1) / TB, TB>>>(row, col, ew);

    // join
    cudaStreamWaitEvent(0, evJoin, 0);

    // layer 1 aggregate (+relu, emit split bf16)
    aggregate_warp_kernel<DH, true, false, true><<<(NN + 7) / 8, 256>>>(
        xw1h, b1, nullptr, h1hi, h1lo);

    // layer 2: GEMM -> aggregate + log_softmax
    mma_gemm_smem_kernel<DH, DOUT><<<GB, 256, SMEM2>>>(h1hi, h1lo, w2hi, w2lo, xw2h, NN);
    aggregate_warp_kernel<DOUT, false, true, false><<<(NN + 7) / 8, 256>>>(
        xw2h, b2, out, nullptr, nullptr);
}

// round 17
// speedup vs baseline: 1.0686x; 1.0651x over previous
#include <cuda_runtime.h>
#include <cuda_bf16.h>
#include <cuda_fp16.h>
#include <cstdint>

// Problem constants (fixed-shape problem)
#define NN   50000
#define EE   1600000
#define DIN  256
#define DH   128
#define DOUT 64

#define SCAN_CHUNK 1024
#define SCAN_NBLK  ((NN + SCAN_CHUNK - 1) / SCAN_CHUNK)   // 49

// ---------------- device scratch ----------------------------------------------
__device__ __nv_bfloat16 g_xw1b[NN * DH];    // x@W1  (bf16: gather + self)
__device__ __nv_bfloat16 g_xw2b[NN * DOUT];  // h1@W2 (bf16)
__device__ float g_deg [NN];
__device__ float g_dinv[NN];
__device__ int   g_cnt   [NN];
__device__ int   g_rowptr[NN + 1];
__device__ int   g_wptr  [NN];
__device__ int   g_blocksum[SCAN_NBLK];
__device__ int   g_blockoff[SCAN_NBLK];
__device__ int   g_src[EE];            // CSR-by-target: source node ids
__device__ float g_ewn[EE];            // dinv[src] * w  per edge (CSR order)
// bf16 activations (row-major [M][K]) — single precision copy (no lo residual)
__device__ __nv_bfloat16 g_xb [NN * DIN];
__device__ __nv_bfloat16 g_h1b[NN * DH];
// split-bf16 weights, transposed [N][K]
__device__ __nv_bfloat16 g_w1hi[DH  * DIN];
__device__ __nv_bfloat16 g_w1lo[DH  * DIN];
__device__ __nv_bfloat16 g_w2hi[DOUT * DH];
__device__ __nv_bfloat16 g_w2lo[DOUT * DH];

// ---------------- setup kernels ------------------------------------------------
__global__ void init_kernel() {
    int i = blockIdx.x * blockDim.x + threadIdx.x;
    if (i < NN) { g_cnt[i] = 0; g_deg[i] = 1.0f; /* self-loop weight */ }
}

__global__ void count_kernel(const int* __restrict__ col, const float* __restrict__ w) {
    int e = blockIdx.x * blockDim.x + threadIdx.x;
    if (e < EE) {
        int c = __ldg(&col[e]);
        atomicAdd(&g_cnt[c], 1);
        atomicAdd(&g_deg[c], __ldg(&w[e]));
    }
}

__global__ void dinv_kernel() {
    int i = blockIdx.x * blockDim.x + threadIdx.x;
    if (i < NN) g_dinv[i] = rsqrtf(g_deg[i]);
}

__global__ __launch_bounds__(SCAN_CHUNK) void scanA_kernel() {
    __shared__ int warpsum[32];
    __shared__ int warpoff[32];
    int tid = threadIdx.x, lane = tid & 31, wid = tid >> 5;
    int gid = blockIdx.x * SCAN_CHUNK + tid;
    int v = (gid < NN) ? g_cnt[gid] : 0;
    int incl = v;
    #pragma unroll
    for (int o = 1; o < 32; o <<= 1) {
        int t = __shfl_up_sync(0xffffffffu, incl, o);
        if (lane >= o) incl += t;
    }
    if (lane == 31) warpsum[wid] = incl;
    __syncthreads();
    if (wid == 0) {
        int s = warpsum[lane];
        int si = s;
        #pragma unroll
        for (int o = 1; o < 32; o <<= 1) {
            int t = __shfl_up_sync(0xffffffffu, si, o);
            if (lane >= o) si += t;
        }
        warpoff[lane] = si - s;
    }
    __syncthreads();
    int ex = warpoff[wid] + incl - v;
    if (gid < NN) g_rowptr[gid] = ex;
    if (tid == SCAN_CHUNK - 1) g_blocksum[blockIdx.x] = ex + v;
}

__global__ void scanB_kernel() {
    if (threadIdx.x == 0) {
        int run = 0;
        #pragma unroll
        for (int b = 0; b < SCAN_NBLK; b++) {
            g_blockoff[b] = run;
            run += g_blocksum[b];
        }
    }
}

__global__ void scanC_kernel() {
    int i = blockIdx.x * blockDim.x + threadIdx.x;
    if (i < NN) {
        int v = g_rowptr[i] + g_blockoff[i / SCAN_CHUNK];
        g_rowptr[i] = v;
        g_wptr[i]   = v;
    }
    if (i == 0) g_rowptr[NN] = EE;
}

__global__ void scatter_kernel(const int* __restrict__ row, const int* __restrict__ col,
                               const float* __restrict__ w) {
    int e = blockIdx.x * blockDim.x + threadIdx.x;
    if (e < EE) {
        int c = __ldg(&col[e]);
        int r = __ldg(&row[e]);
        int p = atomicAdd(&g_wptr[c], 1);
        g_src[p] = r;
        g_ewn[p] = __ldg(&w[e]) * g_dinv[r];
    }
}

// ---- weight split+transpose: W[K][N] fp32 -> hi/lo bf16 [N][K] ----------------
__global__ void convert_w_kernel(const float* __restrict__ W,
                                 __nv_bfloat16* __restrict__ hi,
                                 __nv_bfloat16* __restrict__ lo,
                                 int K, int N)
{
    int i = blockIdx.x * blockDim.x + threadIdx.x;
    if (i < K * N) {
        int k = i / N, n = i % N;
        float v = __ldg(&W[i]);
        __nv_bfloat16 h = __float2bfloat16_rn(v);
        hi[(size_t)n * K + k] = h;
        lo[(size_t)n * K + k] = __float2bfloat16_rn(v - __bfloat162float(h));
    }
}

__device__ __forceinline__ uint32_t pack_bf16x2f(float a, float b) {
    uint16_t lo = __bfloat16_as_ushort(__float2bfloat16_rn(a));
    uint16_t hi = __bfloat16_as_ushort(__float2bfloat16_rn(b));
    return ((uint32_t)hi << 16) | lo;
}

__device__ __forceinline__ float2 bf16x2_to_float2(uint32_t v) {
    float2 f;
    f.x = __uint_as_float(v << 16);
    f.y = __uint_as_float(v & 0xFFFF0000u);
    return f;
}

// ---- activation quantize: A[M][K] fp32 -> single bf16 (hi only) ---------------
__global__ __launch_bounds__(256) void convert_xb_kernel(
    const float* __restrict__ A, __nv_bfloat16* __restrict__ outb, int total4)
{
    int i = blockIdx.x * blockDim.x + threadIdx.x;
    if (i < total4) {
        float4 v = __ldg(&((const float4*)A)[i]);
        uint32_t p01 = pack_bf16x2f(v.x, v.y);
        uint32_t p23 = pack_bf16x2f(v.z, v.w);
        ((uint2*)outb)[i] = make_uint2(p01, p23);
    }
}

// ---------------- mma.sync bf16 GEMM (A single + B split, SMEM, dbl-buffered) --
__device__ __forceinline__ void mma_bf16(float* c, const uint32_t* a, const uint32_t* b) {
    asm volatile(
        "mma.sync.aligned.m16n8k16.row.col.f32.bf16.bf16.f32 "
        "{%0,%1,%2,%3}, {%4,%5,%6,%7}, {%8,%9}, {%0,%1,%2,%3};\n"
        : "+f"(c[0]), "+f"(c[1]), "+f"(c[2]), "+f"(c[3])
        : "r"(a[0]), "r"(a[1]), "r"(a[2]), "r"(a[3]), "r"(b[0]), "r"(b[1]));
}

__device__ __forceinline__ void ldmatrix_x4(uint32_t* r, uint32_t saddr) {
    asm volatile("ldmatrix.sync.aligned.m8n8.x4.shared.b16 {%0,%1,%2,%3}, [%4];"
                 : "=r"(r[0]), "=r"(r[1]), "=r"(r[2]), "=r"(r[3]) : "r"(saddr));
}

__device__ __forceinline__ void ldmatrix_x2(uint32_t* r, uint32_t saddr) {
    asm volatile("ldmatrix.sync.aligned.m8n8.x2.shared.b16 {%0,%1}, [%2];"
                 : "=r"(r[0]), "=r"(r[1]) : "r"(saddr));
}

__device__ __forceinline__ void cp_async16(uint32_t saddr, const void* gaddr) {
    asm volatile("cp.async.ca.shared.global [%0], [%1], 16;"
                 :: "r"(saddr), "l"(gaddr));
}
__device__ __forceinline__ void cp_commit() {
    asm volatile("cp.async.commit_group;");
}
template<int N>
__device__ __forceinline__ void cp_wait() {
    asm volatile("cp.async.wait_group %0;" :: "n"(N));
}

// SMEM rows: 32 bf16 data, stride 40 halfs (80B) -> conflict-free ldmatrix
#define TSTRIDE 40

// CTA tile 64 x NB. 8 warps = 2 rows x 4 cols; warp tile 32 x NB/4.
// A single bf16 (2 MMAs per tile: a*bhi + a*blo). Double-buffered; 2 CTAs/SM.
template<int KTOT, int NB>
__global__ __launch_bounds__(256, 2) void mma_gemm_smem_kernel(
    const __nv_bfloat16* __restrict__ Ab,
    const __nv_bfloat16* __restrict__ Bthi,
    const __nv_bfloat16* __restrict__ Btlo,
    __nv_bfloat16* __restrict__ Cb, int M)
{
    constexpr int NK = KTOT / 32;
    constexpr int NTILES = (NB / 4) / 8;
    constexpr uint32_t SM_A    = 0;
    constexpr uint32_t SM_B_HI = 64 * TSTRIDE * 2;          // 5120
    constexpr uint32_t SM_B_LO = SM_B_HI + NB * TSTRIDE * 2;
    constexpr uint32_t STAGE   = SM_B_LO + NB * TSTRIDE * 2;

    extern __shared__ __align__(16) char smem[];

    int tid  = threadIdx.x;
    int wid  = tid >> 5, lane = tid & 31;
    int g    = lane >> 2, tig = lane & 3;
    int wRow = wid & 1, wCol = wid >> 1;
    int rowBase = blockIdx.x * 64 + wRow * 32;
    int ctaRow  = blockIdx.x * 64;
    int colBase = wCol * (NB / 4);

    uint32_t sbase = 0;
    { uint32_t a; asm("{ .reg .u64 t; cvta.to.shared.u64 t, %1; cvt.u32.u64 %0, t; }"
                      : "=r"(a) : "l"((const void*)smem)); sbase = a; }

    auto load_tile = [&](int kt, int stage) {
        int kk = kt * 32;
        uint32_t sb = sbase + (uint32_t)stage * STAGE;
        // A: 64 rows x 4 chunks(16B) -> one per thread
        {
            int r = tid >> 2, c = tid & 3;
            int gr = min(ctaRow + r, M - 1);
            size_t goff = (size_t)gr * KTOT + kk + c * 8;
            uint32_t soff = (uint32_t)((r * TSTRIDE + c * 8) * 2);
            cp_async16(sb + SM_A + soff, Ab + goff);
        }
        // B: NB rows x 4 chunks per array (hi + lo)
        #pragma unroll
        for (int it = 0; it < (NB * 4) / 256; it++) {
            int chunk = it * 256 + tid;
            int n = chunk >> 2, c = chunk & 3;
            size_t goff = (size_t)n * KTOT + kk + c * 8;
            uint32_t soff = (uint32_t)((n * TSTRIDE + c * 8) * 2);
            cp_async16(sb + SM_B_HI + soff, Bthi + goff);
            cp_async16(sb + SM_B_LO + soff, Btlo + goff);
        }
        cp_commit();
    };

    float c[2][NTILES][4];
    #pragma unroll
    for (int mt = 0; mt < 2; mt++)
        #pragma unroll
        for (int nt = 0; nt < NTILES; nt++)
            #pragma unroll
            for (int i = 0; i < 4; i++) c[mt][nt][i] = 0.f;

    load_tile(0, 0);

    for (int kt = 0; kt < NK; kt++) {
        if (kt + 1 < NK) load_tile(kt + 1, (kt + 1) & 1);
        if (kt + 1 < NK) cp_wait<1>(); else cp_wait<0>();
        __syncthreads();

        uint32_t sb = sbase + (uint32_t)(kt & 1) * STAGE;

        #pragma unroll
        for (int ksub = 0; ksub < 2; ksub++) {
            // A fragments via ldmatrix.x4
            uint32_t af[2][4];
            #pragma unroll
            for (int mt = 0; mt < 2; mt++) {
                int r = wRow * 32 + mt * 16 + (lane & 15);
                uint32_t off = (uint32_t)((r * TSTRIDE + ksub * 16 + ((lane >> 4) & 1) * 8) * 2);
                ldmatrix_x4(af[mt], sb + SM_A + off);
            }
            // B fragments via ldmatrix.x2 from SMEM
            uint32_t bhi[NTILES][2], blo[NTILES][2];
            int l = lane & 15;
            int brow = l & 7;           // n within 8-row tile
            int bmat = (l >> 3) & 1;    // 0: k 0-7, 1: k 8-15
            #pragma unroll
            for (int nt = 0; nt < NTILES; nt++) {
                uint32_t off = (uint32_t)(((colBase + nt * 8 + brow) * TSTRIDE
                                           + ksub * 16 + bmat * 8) * 2);
                ldmatrix_x2(bhi[nt], sb + SM_B_HI + off);
                ldmatrix_x2(blo[nt], sb + SM_B_LO + off);
            }
            #pragma unroll
            for (int mt = 0; mt < 2; mt++)
                #pragma unroll
                for (int nt = 0; nt < NTILES; nt++) {
                    mma_bf16(c[mt][nt], af[mt], bhi[nt]);
                    mma_bf16(c[mt][nt], af[mt], blo[nt]);
                }
        }
        __syncthreads();
    }

    // epilogue: bf16
    #pragma unroll
    for (int mt = 0; mt < 2; mt++) {
        int r0 = rowBase + mt * 16 + g;
        int r1 = r0 + 8;
        #pragma unroll
        for (int nt = 0; nt < NTILES; nt++) {
            int cc = colBase + nt * 8 + tig * 2;
            if (r0 < M)
                *(uint32_t*)&Cb[(size_t)r0 * NB + cc] =
                    pack_bf16x2f(c[mt][nt][0], c[mt][nt][1]);
            if (r1 < M)
                *(uint32_t*)&Cb[(size_t)r1 * NB + cc] =
                    pack_bf16x2f(c[mt][nt][2], c[mt][nt][3]);
        }
    }
}

// ---------------- warp-per-node aggregation, multi-edge vectorized -------------
// bf16 gathers (shift-convert, no CVT pipe): D=128 -> 2 edges per LDG.128;
// D=64 -> 4 edges. fp32 accumulation; out = di*sum + di^2*self + bias.
template<int D, bool RELU, bool SOFTMAX, bool SPLIT>
__global__ __launch_bounds__(256) void aggregate_warp_kernel(
    const __nv_bfloat16* __restrict__ xwb, const float* __restrict__ bias,
    float* __restrict__ out, __nv_bfloat16* __restrict__ outb)
{
    constexpr int WPB = 8;
    int wid  = threadIdx.x >> 5;
    int lane = threadIdx.x & 31;
    int node = blockIdx.x * WPB + wid;
    if (node >= NN) return;

    int p0 = g_rowptr[node], p1 = g_rowptr[node + 1];
    float di = g_dinv[node];
    const uint4* xh = (const uint4*)xwb;          // 8 bf16 per uint4

    if constexpr (D == 128) {
        int half = lane >> 4;        // 0/1: which edge of the pair
        int sub  = lane & 15;        // 16B chunk within the 256B row
        float acc[8];
        #pragma unroll
        for (int t = 0; t < 8; t++) acc[t] = 0.f;

        for (int base = p0; base < p1; base += 32) {
            int idx = base + lane;
            int s = 0; float wv = 0.f;
            if (idx < p1) { s = g_src[idx]; wv = g_ewn[idx]; }
            int c = min(32, p1 - base);
            #pragma unroll 4
            for (int j = 0; j < 16 && 2 * j < c; j++) {
                int e = 2 * j + half;
                int   sj = __shfl_sync(0xffffffffu, s,  e);
                float wj = __shfl_sync(0xffffffffu, wv, e);
                if (e < c) {
                    uint4 hv = __ldg(&xh[(size_t)sj * 16 + sub]);
                    float2 f;
                    f = bf16x2_to_float2(hv.x); acc[0] += wj * f.x; acc[1] += wj * f.y;
                    f = bf16x2_to_float2(hv.y); acc[2] += wj * f.x; acc[3] += wj * f.y;
                    f = bf16x2_to_float2(hv.z); acc[4] += wj * f.x; acc[5] += wj * f.y;
                    f = bf16x2_to_float2(hv.w); acc[6] += wj * f.x; acc[7] += wj * f.y;
                }
            }
        }
        // combine the two edge-halves (lanes L and L+16 hold partials for same feats)
        #pragma unroll
        for (int t = 0; t < 8; t++)
            acc[t] += __shfl_xor_sync(0xffffffffu, acc[t], 16);

        // this lane finalizes feats fb..fb+3
        int fb = sub * 8 + half * 4;
        float d2 = di * di;
        uint2 sv = __ldg((const uint2*)&xwb[(size_t)node * 128 + fb]);
        float2 s01 = bf16x2_to_float2(sv.x);
        float2 s23 = bf16x2_to_float2(sv.y);
        float4 bv  = __ldg((const float4*)&bias[fb]);
        float4 r;
        r.x = di * acc[half * 4 + 0] + d2 * s01.x + bv.x;
        r.y = di * acc[half * 4 + 1] + d2 * s01.y + bv.y;
        r.z = di * acc[half * 4 + 2] + d2 * s23.x + bv.z;
        r.w = di * acc[half * 4 + 3] + d2 * s23.y + bv.w;
        if (RELU) {
            r.x = fmaxf(r.x, 0.f); r.y = fmaxf(r.y, 0.f);
            r.z = fmaxf(r.z, 0.f); r.w = fmaxf(r.w, 0.f);
        }
        if constexpr (SPLIT) {
            uint32_t p01 = pack_bf16x2f(r.x, r.y);
            uint32_t p23 = pack_bf16x2f(r.z, r.w);
            ((uint2*)outb)[(size_t)node * 32 + (fb >> 2)] = make_uint2(p01, p23);
        } else {
            *(float4*)&out[(size_t)node * 128 + fb] = r;
        }
    } else {
        // D == 64: 128B rows, 8 lanes x 16B -> 4 edges per warp-LDG
        int q   = lane >> 3;         // 0..3: which edge of the quad
        int sub = lane & 7;          // 16B chunk within the 128B row
        float acc[8];
        #pragma unroll
        for (int t = 0; t < 8; t++) acc[t] = 0.f;

        for (int base = p0; base < p1; base += 32) {
            int idx = base + lane;
            int s = 0; float wv = 0.f;
            if (idx < p1) { s = g_src[idx]; wv = g_ewn[idx]; }
            int c = min(32, p1 - base);
            #pragma unroll 2
            for (int j = 0; j < 8 && 4 * j < c; j++) {
                int e = 4 * j + q;
                int   sj = __shfl_sync(0xffffffffu, s,  e);
                float wj = __shfl_sync(0xffffffffu, wv, e);
                if (e < c) {
                    uint4 hv = __ldg(&xh[(size_t)sj * 8 + sub]);
                    float2 f;
                    f = bf16x2_to_float2(hv.x); acc[0] += wj * f.x; acc[1] += wj * f.y;
                    f = bf16x2_to_float2(hv.y); acc[2] += wj * f.x; acc[3] += wj * f.y;
                    f = bf16x2_to_float2(hv.z); acc[4] += wj * f.x; acc[5] += wj * f.y;
                    f = bf16x2_to_float2(hv.w); acc[6] += wj * f.x; acc[7] += wj * f.y;
                }
            }
        }
        // combine the four edge-quarters
        #pragma unroll
        for (int t = 0; t < 8; t++) {
            acc[t] += __shfl_xor_sync(0xffffffffu, acc[t], 8);
            acc[t] += __shfl_xor_sync(0xffffffffu, acc[t], 16);
        }

        // this lane finalizes feats fb, fb+1
        int fb = sub * 8 + q * 2;
        float d2 = di * di;
        uint32_t sv = __ldg((const uint32_t*)&xwb[(size_t)node * 64 + fb]);
        float2 sf = bf16x2_to_float2(sv);
        float2 bv = __ldg((const float2*)&bias[fb]);
        float rx = di * acc[q * 2 + 0] + d2 * sf.x + bv.x;
        float ry = di * acc[q * 2 + 1] + d2 * sf.y + bv.y;
        if (RELU) { rx = fmaxf(rx, 0.f); ry = fmaxf(ry, 0.f); }
        if (SOFTMAX) {
            float m = fmaxf(rx, ry);
            #pragma unroll
            for (int o = 16; o > 0; o >>= 1)
                m = fmaxf(m, __shfl_xor_sync(0xffffffffu, m, o));
            float sum = expf(rx - m) + expf(ry - m);
            #pragma unroll
            for (int o = 16; o > 0; o >>= 1)
                sum += __shfl_xor_sync(0xffffffffu, sum, o);
            float ls = m + logf(sum);
            rx -= ls; ry -= ls;
        }
        *(float2*)&out[(size_t)node * 64 + fb] = make_float2(rx, ry);
    }
}

// ---------------- launch -------------------------------------------------------
extern "C" void kernel_launch(void* const* d_in, const int* in_sizes, int n_in,
                              void* d_out, int out_size)
{
    const float* x  = (const float*)d_in[0];
    const int*   ei = (const int*)  d_in[1];
    const float* ew = (const float*)d_in[2];
    const float* W1 = (const float*)d_in[3];
    const float* b1 = (const float*)d_in[4];
    const float* W2 = (const float*)d_in[5];
    const float* b2 = (const float*)d_in[6];
    float* out = (float*)d_out;

    const int* row = ei;          // sources
    const int* col = ei + EE;     // targets

    void *p_xw1b, *p_xw2b, *p_xb, *p_h1b;
    void *p_w1hi, *p_w1lo, *p_w2hi, *p_w2lo;
    cudaGetSymbolAddress(&p_xw1b, g_xw1b);
    cudaGetSymbolAddress(&p_xw2b, g_xw2b);
    cudaGetSymbolAddress(&p_xb,   g_xb);
    cudaGetSymbolAddress(&p_h1b,  g_h1b);
    cudaGetSymbolAddress(&p_w1hi, g_w1hi);
    cudaGetSymbolAddress(&p_w1lo, g_w1lo);
    cudaGetSymbolAddress(&p_w2hi, g_w2hi);
    cudaGetSymbolAddress(&p_w2lo, g_w2lo);
    __nv_bfloat16* xw1b = (__nv_bfloat16*)p_xw1b;
    __nv_bfloat16* xw2b = (__nv_bfloat16*)p_xw2b;
    __nv_bfloat16* xb   = (__nv_bfloat16*)p_xb;
    __nv_bfloat16* h1b  = (__nv_bfloat16*)p_h1b;
    __nv_bfloat16* w1hi = (__nv_bfloat16*)p_w1hi;
    __nv_bfloat16* w1lo = (__nv_bfloat16*)p_w1lo;
    __nv_bfloat16* w2hi = (__nv_bfloat16*)p_w2hi;
    __nv_bfloat16* w2lo = (__nv_bfloat16*)p_w2lo;

    const int TB = 256;
    const int GB = (NN + 63) / 64;   // 782

    // dynamic SMEM: 2 stages of (A 64 rows + B hi/lo NB rows), 80B row stride
    const int SMEM1 = 2 * (64 * TSTRIDE * 2 + 2 * DH   * TSTRIDE * 2);  // 51200
    const int SMEM2 = 2 * (64 * TSTRIDE * 2 + 2 * DOUT * TSTRIDE * 2);  // 30720
    cudaFuncSetAttribute(mma_gemm_smem_kernel<DIN, DH>,
                         cudaFuncAttributeMaxDynamicSharedMemorySize, SMEM1);
    cudaFuncSetAttribute(mma_gemm_smem_kernel<DH, DOUT>,
                         cudaFuncAttributeMaxDynamicSharedMemorySize, SMEM2);

    // fork: CSR branch on default stream, GEMM-prep branch on s2
    cudaStream_t s2;
    cudaStreamCreateWithFlags(&s2, cudaStreamNonBlocking);
    cudaEvent_t evFork, evJoin;
    cudaEventCreateWithFlags(&evFork, cudaEventDisableTiming);
    cudaEventCreateWithFlags(&evJoin, cudaEventDisableTiming);
    cudaEventRecord(evFork, 0);
    cudaStreamWaitEvent(s2, evFork, 0);

    // --- branch A (s2): conversions + GEMM1 ---
    convert_w_kernel<<<(DIN * DH   + TB - 1) / TB, TB, 0, s2>>>(W1, w1hi, w1lo, DIN, DH);
    convert_w_kernel<<<(DH  * DOUT + TB - 1) / TB, TB, 0, s2>>>(W2, w2hi, w2lo, DH, DOUT);
    convert_xb_kernel<<<(NN * DIN / 4 + TB - 1) / TB, TB, 0, s2>>>(x, xb, NN * DIN / 4);
    mma_gemm_smem_kernel<DIN, DH><<<GB, 256, SMEM1, s2>>>(xb, w1hi, w1lo, xw1b, NN);
    cudaEventRecord(evJoin, s2);

    // --- branch B (default): CSR build + degree norm ---
    init_kernel   <<<(NN + TB - 1) / TB, TB>>>();
    count_kernel  <<<(EE + TB - 1) / TB, TB>>>(col, ew);
    dinv_kernel   <<<(NN + TB - 1) / TB, TB>>>();
    scanA_kernel  <<<SCAN_NBLK, SCAN_CHUNK>>>();
    scanB_kernel  <<<1, 32>>>();
    scanC_kernel  <<<(NN + TB - 1) / TB, TB>>>();
    scatter_kernel<<<(EE + TB - 1) / TB, TB>>>(row, col, ew);

    // join
    cudaStreamWaitEvent(0, evJoin, 0);

    // layer 1 aggregate (+relu, emit bf16 h1 — exact bf16, no residual)
    aggregate_warp_kernel<DH, true, false, true><<<(NN + 7) / 8, 256>>>(
        xw1b, b1, nullptr, h1b);

    // layer 2: GEMM (A = bf16 h1, 2-term) -> aggregate + log_softmax
    mma_gemm_smem_kernel<DH, DOUT><<<GB, 256, SMEM2>>>(h1b, w2hi, w2lo, xw2b, NN);
    aggregate_warp_kernel<DOUT, false, true, false><<<(NN + 7) / 8, 256>>>(
        xw2b, b2, out, nullptr);
}